// round 15
// baseline (speedup 1.0000x reference)
#include <cuda_runtime.h>
#include <cstdint>

// Problem constants
#define BB 64       // batch
#define KK 4096     // dim_in
#define OO 4096     // dim_out
#define OT 16       // output columns per strip
#define NSTRIP (OO / OT)    // 256
#define SLABS  4            // k-split
#define SKW    32           // kw per slab (1024 k-rows)

// x bits, transposed: [kw][b]
__device__ uint32_t g_xbitsT[(KK / 32) * BB];             // 32 KB
// partial popc sums: [slab][strip][b][OT]
__device__ uint32_t g_partial[SLABS * NSTRIP * BB * OT];  // 4 MB
// strip completion counters (self-resetting; zero at load)
__device__ int g_scnt[NSTRIP];

// Robust 0/1 extraction: int32 {0,1} (bit 0) or float32 {0.0f,1.0f} (bit 23).
__device__ __forceinline__ uint32_t bit01(uint32_t w) {
    return (w | (w >> 23)) & 1u;
}

// ---------------------------------------------------------------------------
// Pack x via warp ballot: one thread per element (proven R9 kernel).
// ---------------------------------------------------------------------------
__global__ void __launch_bounds__(256) pack_x_kernel(const uint32_t* __restrict__ x) {
    const int g = blockIdx.x * 256 + threadIdx.x;   // 0..262143 -> (b, k)
    const uint32_t w = __ballot_sync(0xFFFFFFFFu, bit01(x[g]));
    if ((threadIdx.x & 31) == 0)
        g_xbitsT[((g & (KK - 1)) >> 5) * BB + (g >> 12)] = w;
}

// ---------------------------------------------------------------------------
// Partial kernel with fused epilogue: 1024 blocks x 256 threads.
// STRIP-major indexing (R9's proven layout): strip = bid & 255, slab = bid>>8.
//   phase 1: pack [1024 k-rows x 16 cols] into a 2KB bit tile (FULL unroll
//            -> 32 independent uint2 loads in flight per thread)
//   phase 2: XNOR-popcount vs x bits, store partial sums
//   finisher: 4th-arriving slab block reduces partials + thresholds + writes.
// ---------------------------------------------------------------------------
__global__ void __launch_bounds__(256) xnor_partial_kernel(
    const uint32_t* __restrict__ masks,  // [KK][OO] 0/1 words
    const int*      __restrict__ thr,    // [OO] int32
    float*          __restrict__ out)    // [BB][OO] float32 0/1
{
    __shared__ uint32_t tile[SKW * OT];   // 2 KB, layout [kw][o]
    __shared__ int s_last;

    const int t     = threadIdx.x;
    const int strip = blockIdx.x & (NSTRIP - 1);
    const int slab  = blockIdx.x >> 8;
    const int o0    = strip * OT;
    const int kw0   = slab * SKW;

    // ---------------- phase 1: pack mask slab-strip into shared bits -------
    // thread -> (op = column pair 0..7, kwl = 0..31)
    {
        const int op  = t & 7;
        const int kwl = t >> 3;
        const uint2* base = reinterpret_cast<const uint2*>(
            masks + (size_t)((kw0 + kwl) * 32) * OO + o0 + op * 2);
        uint32_t a0 = 0, a1 = 0;
        #pragma unroll
        for (int j = 0; j < 32; j++) {
            uint2 m = base[(size_t)j * (OO / 2)];
            a0 |= bit01(m.x) << j;
            a1 |= bit01(m.y) << j;
        }
        *reinterpret_cast<uint2*>(&tile[kwl * OT + op * 2]) = make_uint2(a0, a1);
    }
    __syncthreads();

    // ---------------- phase 2: XNOR popcount over the slab ------------------
    const int lane = t & 31;
    const int warp = t >> 5;
    const int half = warp & 1;        // which 32 batches
    const int oset = warp >> 1;       // 0..3 -> 4 columns each
    const int b    = half * 32 + lane;

    int acc[4] = {0, 0, 0, 0};
    const uint4* t4 = reinterpret_cast<const uint4*>(tile);

    #pragma unroll
    for (int ck = 0; ck < SKW / 8; ck++) {
        uint32_t xr[8];
        #pragma unroll
        for (int j = 0; j < 8; j++)
            xr[j] = g_xbitsT[(kw0 + ck * 8 + j) * BB + b];

        #pragma unroll
        for (int j = 0; j < 8; j++) {
            const uint32_t xv = xr[j];
            uint4 m = t4[(ck * 8 + j) * 4 + oset];   // broadcast
            acc[0] += __popc(xv ^ m.x);
            acc[1] += __popc(xv ^ m.y);
            acc[2] += __popc(xv ^ m.z);
            acc[3] += __popc(xv ^ m.w);
        }
    }

    // partial store: [slab][strip][b][oset*4..+3]
    uint32_t* pp = &g_partial[(((size_t)slab * NSTRIP + strip) * BB + b) * OT + oset * 4];
    *reinterpret_cast<uint4*>(pp) =
        make_uint4((uint32_t)acc[0], (uint32_t)acc[1],
                   (uint32_t)acc[2], (uint32_t)acc[3]);
    __threadfence();
    __syncthreads();

    // ---------------- finisher: last slab-block of this strip ---------------
    if (t == 0) s_last = (atomicAdd(&g_scnt[strip], 1) == SLABS - 1);
    __syncthreads();

    if (s_last) {
        if (t == 0) g_scnt[strip] = 0;    // reset for next graph replay
        __threadfence();                   // acquire all slabs' partials
        const int o_l = t & 15;
        const int o   = o0 + o_l;
        const int th  = thr[o];
        #pragma unroll
        for (int i = 0; i < 4; i++) {
            const int bb = (t >> 4) + i * 16;
            int s = 0;
            #pragma unroll
            for (int sl = 0; sl < SLABS; sl++)
                s += (int)g_partial[(((size_t)sl * NSTRIP + strip) * BB + bb) * OT + o_l];
            out[(size_t)bb * OO + o] = ((KK - s) > th) ? 1.0f : 0.0f;
        }
    }
}

// ---------------------------------------------------------------------------
extern "C" void kernel_launch(void* const* d_in, const int* in_sizes, int n_in,
                              void* d_out, int out_size) {
    // Identify inputs by element count (robust to ordering)
    const void* x     = d_in[0];
    const void* masks = d_in[1];
    const int*  thr   = (const int*)d_in[2];
    for (int i = 0; i < n_in; i++) {
        if      (in_sizes[i] == KK * OO) masks = d_in[i];
        else if (in_sizes[i] == BB * KK) x     = d_in[i];
        else if (in_sizes[i] == OO)      thr   = (const int*)d_in[i];
    }

    pack_x_kernel<<<(BB * KK) / 256, 256>>>((const uint32_t*)x);
    xnor_partial_kernel<<<NSTRIP * SLABS, 256>>>((const uint32_t*)masks,
                                                 thr, (float*)d_out);
}

// round 16
// speedup vs baseline: 1.1506x; 1.1506x over previous
#include <cuda_runtime.h>
#include <cstdint>

// Problem constants
#define BB 64       // batch
#define KK 4096     // dim_in
#define OO 4096     // dim_out
#define OT 32       // output columns per strip (128B rows -> full L2 lines)
#define NSTRIP (OO / OT)    // 128
#define SLABS  8            // k-split
#define SKW    16           // kw per slab (512 k-rows)

// x bits, transposed: [kw][b]
__device__ uint32_t g_xbitsT[(KK / 32) * BB];             // 32 KB
// packed partial popc sums: [slab][strip][b][16]  (lo=col o_l, hi=col o_l+16)
__device__ uint32_t g_partial[SLABS * NSTRIP * BB * 16];  // 4 MB

// Robust 0/1 extraction: int32 {0,1} (bit 0) or float32 {0.0f,1.0f} (bit 23).
__device__ __forceinline__ uint32_t bit01(uint32_t w) {
    return (w | (w >> 23)) & 1u;
}

// ---------------------------------------------------------------------------
// Pack x via warp ballot: one thread per element (proven R9 kernel).
// ---------------------------------------------------------------------------
__global__ void __launch_bounds__(256) pack_x_kernel(const uint32_t* __restrict__ x) {
    const int g = blockIdx.x * 256 + threadIdx.x;   // 0..262143 -> (b, k)
    const uint32_t w = __ballot_sync(0xFFFFFFFFu, bit01(x[g]));
    if ((threadIdx.x & 31) == 0)
        g_xbitsT[((g & (KK - 1)) >> 5) * BB + (g >> 12)] = w;
}

// ---------------------------------------------------------------------------
// Partial kernel: 1024 blocks (128 strips x 8 slabs) x 256 threads.
//   phase 1: pack [512 k-rows x 32 cols] into a 2KB bit tile. Warp lanes
//            (op=t&15) span a FULL 128B line -> 2 complete L2 lines per LDG.64
//   phase 2: XNOR-popcount vs x bits, store u16-packed partial sums
// ---------------------------------------------------------------------------
__global__ void __launch_bounds__(256) xnor_partial_kernel(
    const uint32_t* __restrict__ masks)  // [KK][OO] 0/1 words
{
    __shared__ uint32_t tile[SKW * OT];   // 2 KB, layout [kw][o]

    const int t     = threadIdx.x;
    const int strip = blockIdx.x & (NSTRIP - 1);
    const int slab  = blockIdx.x >> 7;
    const int o0    = strip * OT;
    const int kw0   = slab * SKW;

    // ---------------- phase 1: pack mask slab-strip into shared bits -------
    // thread -> (op = column pair 0..15, kwl = 0..15)
    {
        const int op  = t & 15;
        const int kwl = t >> 4;
        const uint2* base = reinterpret_cast<const uint2*>(
            masks + (size_t)((kw0 + kwl) * 32) * OO + o0 + op * 2);
        uint32_t a0 = 0, a1 = 0;
        #pragma unroll 8
        for (int j = 0; j < 32; j++) {
            uint2 m = base[(size_t)j * (OO / 2)];
            a0 |= bit01(m.x) << j;
            a1 |= bit01(m.y) << j;
        }
        *reinterpret_cast<uint2*>(&tile[kwl * OT + op * 2]) = make_uint2(a0, a1);
    }
    __syncthreads();

    // ---------------- phase 2: XNOR popcount over the slab ------------------
    const int lane = t & 31;
    const int warp = t >> 5;
    const int half = warp & 1;        // which 32 batches
    const int oset = warp >> 1;       // 0..3 -> cols {oset*4..+3} and {+16}
    const int b    = half * 32 + lane;

    int acc[8] = {0, 0, 0, 0, 0, 0, 0, 0};
    const uint4* t4 = reinterpret_cast<const uint4*>(tile);

    #pragma unroll
    for (int ck = 0; ck < SKW / 8; ck++) {
        uint32_t xr[8];
        #pragma unroll
        for (int j = 0; j < 8; j++)
            xr[j] = g_xbitsT[(kw0 + ck * 8 + j) * BB + b];

        #pragma unroll
        for (int j = 0; j < 8; j++) {
            const uint32_t xv = xr[j];
            const int row = (ck * 8 + j) * 8;       // uint4s per tile row = 8
            uint4 m0 = t4[row + oset];              // cols oset*4..+3
            uint4 m1 = t4[row + 4 + oset];          // cols 16+oset*4..+3
            acc[0] += __popc(xv ^ m0.x);
            acc[1] += __popc(xv ^ m0.y);
            acc[2] += __popc(xv ^ m0.z);
            acc[3] += __popc(xv ^ m0.w);
            acc[4] += __popc(xv ^ m1.x);
            acc[5] += __popc(xv ^ m1.y);
            acc[6] += __popc(xv ^ m1.z);
            acc[7] += __popc(xv ^ m1.w);
        }
    }

    // packed partial store: lo = col o_l, hi = col o_l+16  (counts <= 512)
    uint32_t* pp = &g_partial[(((size_t)slab * NSTRIP + strip) * BB + b) * 16 + oset * 4];
    *reinterpret_cast<uint4*>(pp) = make_uint4(
        (uint32_t)acc[0] | ((uint32_t)acc[4] << 16),
        (uint32_t)acc[1] | ((uint32_t)acc[5] << 16),
        (uint32_t)acc[2] | ((uint32_t)acc[6] << 16),
        (uint32_t)acc[3] | ((uint32_t)acc[7] << 16));
}

// ---------------------------------------------------------------------------
// Epilogue: sum 8 packed slab partials (no carry: sums <= 4096), threshold,
// write float out. 128 blocks x 256 threads; each thread does 4 batches.
// ---------------------------------------------------------------------------
__global__ void __launch_bounds__(256) epilogue_kernel(
    const int* __restrict__ thr,    // [OO] int32
    float*     __restrict__ out)    // [BB][OO] float32 0/1
{
    const int t     = threadIdx.x;
    const int strip = blockIdx.x;
    const int o_l   = t & 15;
    const int oA    = strip * OT + o_l;
    const int oB    = oA + 16;
    const int thA   = thr[oA];
    const int thB   = thr[oB];

    #pragma unroll
    for (int i = 0; i < 4; i++) {
        const int b = (t >> 4) + i * 16;
        uint32_t s = 0;
        #pragma unroll
        for (int sl = 0; sl < SLABS; sl++)
            s += g_partial[(((size_t)sl * NSTRIP + strip) * BB + b) * 16 + o_l];
        const int lo = (int)(s & 0xFFFFu);   // hamming, col oA
        const int hi = (int)(s >> 16);       // hamming, col oB
        out[(size_t)b * OO + oA] = ((KK - lo) > thA) ? 1.0f : 0.0f;
        out[(size_t)b * OO + oB] = ((KK - hi) > thB) ? 1.0f : 0.0f;
    }
}

// ---------------------------------------------------------------------------
extern "C" void kernel_launch(void* const* d_in, const int* in_sizes, int n_in,
                              void* d_out, int out_size) {
    // Identify inputs by element count (robust to ordering)
    const void* x     = d_in[0];
    const void* masks = d_in[1];
    const int*  thr   = (const int*)d_in[2];
    for (int i = 0; i < n_in; i++) {
        if      (in_sizes[i] == KK * OO) masks = d_in[i];
        else if (in_sizes[i] == BB * KK) x     = d_in[i];
        else if (in_sizes[i] == OO)      thr   = (const int*)d_in[i];
    }

    pack_x_kernel<<<(BB * KK) / 256, 256>>>((const uint32_t*)x);
    xnor_partial_kernel<<<NSTRIP * SLABS, 256>>>((const uint32_t*)masks);
    epilogue_kernel<<<NSTRIP, 256>>>(thr, (float*)d_out);
}